// round 14
// baseline (speedup 1.0000x reference)
#include <cuda_runtime.h>
#include <cuda_fp16.h>
#include <cstdint>
#include <math.h>

// Problem constants
#define BB     4
#define NN     4096
#define MM     32768
#define DTOK   512
#define DATOM  128
#define NHEAD  4
#define DH     32
#define WMAX   16
#define LNEPS  1e-5f

#define NTOK   (BB * NN)    // 16384 token rows
#define NATOM  (BB * MM)    // 131072 atom rows

// Single dynamic smem symbol shared by all kernels (cast locally).
extern __shared__ char dyn_smem[];

// -------- scratch (device globals; no allocations allowed) --------
__device__ __half g_K[(size_t)NATOM * DATOM];
__device__ __half g_V[(size_t)NATOM * DATOM];
__device__ float g_Q[(size_t)NTOK * DATOM];
__device__ float g_G[(size_t)NTOK * DATOM];
__device__ __half g_U[(size_t)NTOK * DATOM];
__device__ __half g_sn[(size_t)NTOK * DTOK];     // LN(s) fp16
__device__ __half g_an[(size_t)NATOM * DATOM];   // LN(a) fp16
// fp16 weights (converted once per launch by wprep_kernel)
__device__ __half g_hwk[DATOM * DATOM];
__device__ __half g_hwv[DATOM * DATOM];
__device__ __half g_hwq[DTOK * DATOM];
__device__ __half g_hwg[DTOK * DATOM];
__device__ __half g_hwo[DATOM * DTOK];

__device__ __forceinline__ float warp_sum(float v) {
#pragma unroll
    for (int o = 16; o > 0; o >>= 1) v += __shfl_xor_sync(0xffffffffu, v, o);
    return v;
}
__device__ __forceinline__ uint32_t smem_u32(const void* p) {
    uint32_t a;
    asm("{ .reg .u64 t; cvta.to.shared.u64 t, %1; cvt.u32.u64 %0, t; }"
        : "=r"(a) : "l"(p));
    return a;
}
__device__ __forceinline__ uint32_t pack_h2(float a, float b) {
    __half2 t = __floats2half2_rn(a, b);
    return *(uint32_t*)&t;
}

// ---- cp.async helpers (sm_80+) ----
#define CP_ASYNC16(dst, src) \
    asm volatile("cp.async.cg.shared.global [%0], [%1], 16;" \
                 :: "r"((uint32_t)(dst)), "l"(src))
#define CP_COMMIT() asm volatile("cp.async.commit_group;" ::: "memory")
#define CP_WAIT0()  asm volatile("cp.async.wait_group 0;" ::: "memory")
#define CP_WAIT1()  asm volatile("cp.async.wait_group 1;" ::: "memory")

// ---- warp-level MMA helpers ----
__device__ __forceinline__ void ldm4(uint32_t* d, uint32_t addr) {
    asm volatile("ldmatrix.sync.aligned.m8n8.x4.shared.b16 {%0,%1,%2,%3}, [%4];"
                 : "=r"(d[0]), "=r"(d[1]), "=r"(d[2]), "=r"(d[3]) : "r"(addr));
}
__device__ __forceinline__ void ldm4t(uint32_t* d, uint32_t addr) {
    asm volatile("ldmatrix.sync.aligned.m8n8.x4.trans.shared.b16 {%0,%1,%2,%3}, [%4];"
                 : "=r"(d[0]), "=r"(d[1]), "=r"(d[2]), "=r"(d[3]) : "r"(addr));
}
__device__ __forceinline__ void mma16816(float* c, const uint32_t* a,
                                         uint32_t b0, uint32_t b1) {
    asm volatile(
        "mma.sync.aligned.m16n8k16.row.col.f32.f16.f16.f32 "
        "{%0,%1,%2,%3}, {%4,%5,%6,%7}, {%8,%9}, {%0,%1,%2,%3};"
        : "+f"(c[0]), "+f"(c[1]), "+f"(c[2]), "+f"(c[3])
        : "r"(a[0]), "r"(a[1]), "r"(a[2]), "r"(a[3]), "r"(b0), "r"(b1));
}

// Shared tile geometry (128x128 fp16 tiles, padded)
#define KV_STRIDE_B 272                   // bytes per smem row (136 halves)
#define KV_TILE_B   (128 * KV_STRIDE_B)   // 34816 bytes
#define STG_STRIDE  136                   // floats per staged row
#define STG_STRIDE_H 136                  // halves per fp16 staged row

#define OFF_A    0
#define OFF_B    KV_TILE_B
#define GEMM_SMEM (2 * KV_TILE_B)   // 69632 bytes

// kv multi-tile layout: B + A0 + A1
#define KVT      4                         // M-tiles per kv block
#define KOFF_B   0
#define KOFF_A0  KV_TILE_B
#define KOFF_A1  (2 * KV_TILE_B)
#define KV_SMEM  (3 * KV_TILE_B)           // 104448 bytes

// ==================================================================
// Kernel 0: convert all weights to fp16 once.
// ==================================================================
__global__ void wprep_kernel(const float* __restrict__ wq,
                             const float* __restrict__ wk,
                             const float* __restrict__ wv,
                             const float* __restrict__ wg,
                             const float* __restrict__ wo) {
    int i = blockIdx.x * 256 + threadIdx.x;   // 0..65535
    if (i < DATOM * DATOM) {
        g_hwk[i] = __float2half_rn(wk[i]);
        g_hwv[i] = __float2half_rn(wv[i]);
    }
    g_hwq[i] = __float2half_rn(wq[i]);
    g_hwg[i] = __float2half_rn(wg[i]);
    g_hwo[i] = __float2half_rn(wo[i]);
}

// ==================================================================
// Kernel 1: LN(s) -> g_sn fp16. One warp per row of 512.
// ==================================================================
__global__ void s_prep_kernel(const float* __restrict__ s,
                              const float* __restrict__ lng,
                              const float* __restrict__ lnb) {
    int row  = blockIdx.x * 8 + (threadIdx.x >> 5);
    int lane = threadIdx.x & 31;
    const float4* p = (const float4*)(s + (size_t)row * DTOK);
    float4 v[4];
    float sum = 0.f, sq = 0.f;
#pragma unroll
    for (int j = 0; j < 4; j++) {
        v[j] = p[lane + 32 * j];
        sum += v[j].x + v[j].y + v[j].z + v[j].w;
        sq  += v[j].x * v[j].x + v[j].y * v[j].y + v[j].z * v[j].z + v[j].w * v[j].w;
    }
    sum = warp_sum(sum);
    sq  = warp_sum(sq);
    float mu = sum * (1.f / DTOK);
    float rs = rsqrtf(sq * (1.f / DTOK) - mu * mu + LNEPS);
    __half* dst = g_sn + (size_t)row * DTOK;
#pragma unroll
    for (int j = 0; j < 4; j++) {
        int c = (lane + 32 * j) * 4;
        float4 gv = *(const float4*)(lng + c);
        float4 bv = *(const float4*)(lnb + c);
        float n0 = (v[j].x - mu) * rs * gv.x + bv.x;
        float n1 = (v[j].y - mu) * rs * gv.y + bv.y;
        float n2 = (v[j].z - mu) * rs * gv.z + bv.z;
        float n3 = (v[j].w - mu) * rs * gv.w + bv.w;
        *(uint2*)(dst + c) = make_uint2(pack_h2(n0, n1), pack_h2(n2, n3));
    }
}

// ==================================================================
// Kernel 2: LN(a) -> g_an fp16. One warp per row of 128.
// ==================================================================
__global__ void a_prep_kernel(const float* __restrict__ a,
                              const float* __restrict__ lng,
                              const float* __restrict__ lnb) {
    int row  = blockIdx.x * 8 + (threadIdx.x >> 5);
    int lane = threadIdx.x & 31;
    float4 v = *(const float4*)(a + (size_t)row * DATOM + lane * 4);
    float sum = warp_sum(v.x + v.y + v.z + v.w);
    float sq  = warp_sum(v.x * v.x + v.y * v.y + v.z * v.z + v.w * v.w);
    float mu  = sum * (1.f / 128.f);
    float rs  = rsqrtf(sq * (1.f / 128.f) - mu * mu + LNEPS);
    float4 gv = ((const float4*)lng)[lane];
    float4 bv = ((const float4*)lnb)[lane];
    float n0 = (v.x - mu) * rs * gv.x + bv.x;
    float n1 = (v.y - mu) * rs * gv.y + bv.y;
    float n2 = (v.z - mu) * rs * gv.z + bv.z;
    float n3 = (v.w - mu) * rs * gv.w + bv.w;
    *(uint2*)(g_an + (size_t)row * DATOM + lane * 4) =
        make_uint2(pack_h2(n0, n1), pack_h2(n2, n3));
}

// ==================================================================
// Kernel 3: one of {K,V} per block (blockIdx.y). KVT M-tiles per
// block with resident B and double-buffered A (cp.async pipeline).
// ==================================================================
__global__ void __launch_bounds__(256, 2)
kv_mma_kernel() {
    char* sm = dyn_smem;
    uint32_t sbase = smem_u32(sm);
    int tid = threadIdx.x;
    int warp = tid >> 5, lane = tid & 31;
    size_t rowbase0 = (size_t)blockIdx.x * (128 * KVT);
    const __half* w = blockIdx.y ? g_hwv : g_hwk;
    __half* dst     = blockIdx.y ? g_V : g_K;

    // G0: B + A0
#pragma unroll
    for (int t = 0; t < 8; t++) {
        int j   = tid + t * 256;
        int row = j >> 4;
        int c8  = (j & 15) * 8;
        uint32_t off = (uint32_t)row * KV_STRIDE_B + c8 * 2;
        CP_ASYNC16(sbase + KOFF_B + off, w + row * DATOM + c8);
        CP_ASYNC16(sbase + KOFF_A0 + off, g_an + (rowbase0 + row) * DATOM + c8);
    }
    CP_COMMIT();
    // G1: A1
#pragma unroll
    for (int t = 0; t < 8; t++) {
        int j   = tid + t * 256;
        int row = j >> 4;
        int c8  = (j & 15) * 8;
        uint32_t off = (uint32_t)row * KV_STRIDE_B + c8 * 2;
        CP_ASYNC16(sbase + KOFF_A1 + off,
                   g_an + (rowbase0 + 128 + row) * DATOM + c8);
    }
    CP_COMMIT();

    int wm = warp & 3;
    int wn = warp >> 2;
    int lr = lane & 15;
    int lc = lane >> 4;
    uint32_t aRel  = (uint32_t)(wm * 32 + lr) * KV_STRIDE_B + lc * 16;
    uint32_t bAddr = sbase + KOFF_B + (uint32_t)lr * KV_STRIDE_B +
                     (wn * 64 + lc * 8) * 2;

#pragma unroll 1
    for (int tt = 0; tt < KVT; tt++) {
        if (tt < KVT - 1) { CP_WAIT1(); } else { CP_WAIT0(); }
        __syncthreads();
        uint32_t abase = sbase + ((tt & 1) ? KOFF_A1 : KOFF_A0);
        uint32_t aAddr = abase + aRel;

        float c[2][8][4];
#pragma unroll
        for (int mt = 0; mt < 2; mt++)
#pragma unroll
            for (int nt = 0; nt < 8; nt++)
#pragma unroll
                for (int e = 0; e < 4; e++) c[mt][nt][e] = 0.f;

#pragma unroll
        for (int ks = 0; ks < 8; ks++) {
            uint32_t ak = aAddr + ks * 32;
            uint32_t bk = bAddr + ks * 16 * KV_STRIDE_B;
            uint32_t aF[2][4];
            ldm4(aF[0], ak);
            ldm4(aF[1], ak + 16 * KV_STRIDE_B);
            uint32_t b[4][4];
#pragma unroll
            for (int i = 0; i < 4; i++) ldm4t(b[i], bk + i * 32);
#pragma unroll
            for (int mt = 0; mt < 2; mt++)
#pragma unroll
                for (int i = 0; i < 4; i++) {
                    mma16816(c[mt][2 * i],     aF[mt], b[i][0], b[i][1]);
                    mma16816(c[mt][2 * i + 1], aF[mt], b[i][2], b[i][3]);
                }
        }
        __syncthreads();   // all warps done reading this A buffer
        // stage fp16 into the consumed A buffer
        {
            __half* stg = (__half*)(sm + ((tt & 1) ? KOFF_A1 : KOFF_A0));
            int cr = lane >> 2, cc2 = (lane & 3) * 2;
#pragma unroll
            for (int mt = 0; mt < 2; mt++) {
                int r0 = wm * 32 + mt * 16 + cr;
#pragma unroll
                for (int nt = 0; nt < 8; nt++) {
                    int cc = wn * 64 + nt * 8 + cc2;
                    *(__half2*)&stg[r0 * STG_STRIDE_H + cc] =
                        __floats2half2_rn(c[mt][nt][0], c[mt][nt][1]);
                    *(__half2*)&stg[(r0 + 8) * STG_STRIDE_H + cc] =
                        __floats2half2_rn(c[mt][nt][2], c[mt][nt][3]);
                }
            }
            __syncthreads();
            size_t rowb = rowbase0 + (size_t)tt * 128;
#pragma unroll
            for (int t = 0; t < 8; t++) {
                int j  = tid + t * 256;
                int r  = j >> 4;
                int c8 = (j & 15) * 8;
                *(uint4*)&dst[(rowb + r) * DATOM + c8] =
                    *(uint4*)&stg[r * STG_STRIDE_H + c8];
            }
            __syncthreads();   // smem reads done before refill
        }
        // prefetch A[tt+2] into this buffer
        if (tt + 2 < KVT) {
            uint32_t abuf = sbase + ((tt & 1) ? KOFF_A1 : KOFF_A0);
            size_t rown = rowbase0 + (size_t)(tt + 2) * 128;
#pragma unroll
            for (int t = 0; t < 8; t++) {
                int j   = tid + t * 256;
                int row = j >> 4;
                int c8  = (j & 15) * 8;
                CP_ASYNC16(abuf + (uint32_t)row * KV_STRIDE_B + c8 * 2,
                           g_an + (rown + row) * DATOM + c8);
            }
            CP_COMMIT();
        }
    }
}

// ==================================================================
// Kernel 4: one of {Q,G} per block (blockIdx.y). K = 512 in 4 chunks.
// ==================================================================
__global__ void __launch_bounds__(256, 2)
qg_mma_kernel() {
    char* sm = dyn_smem;
    uint32_t sbase = smem_u32(sm);
    int tid = threadIdx.x;
    int warp = tid >> 5, lane = tid & 31;
    size_t rowbase = (size_t)blockIdx.x * 128;
    const __half* w = blockIdx.y ? g_hwg : g_hwq;
    float* dst      = blockIdx.y ? g_G : g_Q;

    int wm = warp & 3;
    int wn = warp >> 2;
    int lr = lane & 15;
    int lc = lane >> 4;
    uint32_t aAddr = sbase + OFF_A + (uint32_t)(wm * 32 + lr) * KV_STRIDE_B + lc * 16;
    uint32_t bAddr = sbase + OFF_B + (uint32_t)lr * KV_STRIDE_B + (wn * 64 + lc * 8) * 2;

    float c[2][8][4];
#pragma unroll
    for (int mt = 0; mt < 2; mt++)
#pragma unroll
        for (int nt = 0; nt < 8; nt++)
#pragma unroll
            for (int e = 0; e < 4; e++) c[mt][nt][e] = 0.f;

#pragma unroll 1
    for (int kc = 0; kc < 4; kc++) {
        int k0 = kc * 128;
#pragma unroll
        for (int t = 0; t < 8; t++) {
            int j   = tid + t * 256;
            int row = j >> 4;
            int c8  = (j & 15) * 8;
            uint32_t off = (uint32_t)row * KV_STRIDE_B + c8 * 2;
            CP_ASYNC16(sbase + OFF_A + off,
                       g_sn + (rowbase + row) * DTOK + k0 + c8);
            CP_ASYNC16(sbase + OFF_B + off,
                       w + (size_t)(k0 + row) * DATOM + c8);
        }
        CP_COMMIT();
        CP_WAIT0();
        __syncthreads();
#pragma unroll
        for (int ks = 0; ks < 8; ks++) {
            uint32_t ak = aAddr + ks * 32;
            uint32_t bk = bAddr + ks * 16 * KV_STRIDE_B;
            uint32_t aF[2][4];
            ldm4(aF[0], ak);
            ldm4(aF[1], ak + 16 * KV_STRIDE_B);
            uint32_t b[4][4];
#pragma unroll
            for (int i = 0; i < 4; i++) ldm4t(b[i], bk + i * 32);
#pragma unroll
            for (int mt = 0; mt < 2; mt++)
#pragma unroll
                for (int i = 0; i < 4; i++) {
                    mma16816(c[mt][2 * i],     aF[mt], b[i][0], b[i][1]);
                    mma16816(c[mt][2 * i + 1], aF[mt], b[i][2], b[i][3]);
                }
        }
        __syncthreads();
    }
    {
        float* stg = (float*)sm;
        int cr = lane >> 2, cc2 = (lane & 3) * 2;
#pragma unroll
        for (int mt = 0; mt < 2; mt++) {
            int r0 = wm * 32 + mt * 16 + cr;
#pragma unroll
            for (int nt = 0; nt < 8; nt++) {
                int cc = wn * 64 + nt * 8 + cc2;
                *(float2*)&stg[r0 * STG_STRIDE + cc] =
                    make_float2(c[mt][nt][0], c[mt][nt][1]);
                *(float2*)&stg[(r0 + 8) * STG_STRIDE + cc] =
                    make_float2(c[mt][nt][2], c[mt][nt][3]);
            }
        }
        __syncthreads();
#pragma unroll
        for (int t = 0; t < 16; t++) {
            int j  = tid + t * 256;
            int r  = j >> 5;
            int c4 = (j & 31) * 4;
            *(float4*)&dst[(rowbase + r) * DATOM + c4] =
                *(float4*)&stg[r * STG_STRIDE + c4];
        }
    }
}

// ==================================================================
// Kernel 5: ragged window attention + gate. WARP PER TOKEN.
// ==================================================================
__global__ void __launch_bounds__(256, 8)
attn_gate_kernel(const int* __restrict__ starts, const int* __restrict__ counts,
                 const float* __restrict__ tmask) {
    int warp = threadIdx.x >> 5, lane = threadIdx.x & 31;
    int bt = blockIdx.x * 8 + warp;      // token index
    int b  = bt >> 12;                   // batch (N = 4096)
    int start = starts[bt];
    int count = counts[bt];
    const float scale = 0.17677669529663687f;   // 1/sqrt(32)

    float4 q = *(const float4*)(g_Q + (size_t)bt * DATOM + lane * 4);
    const __half* kb = g_K + ((size_t)b * MM + start) * DATOM;

    float sc[WMAX];
#pragma unroll
    for (int w = 0; w < WMAX; w++) {
        float d = -1e30f;
        if (w < count) {
            uint2 raw = *(const uint2*)(kb + (size_t)w * DATOM + lane * 4);
            float2 f01 = __half22float2(*(__half2*)&raw.x);
            float2 f23 = __half22float2(*(__half2*)&raw.y);
            float t = q.x * f01.x + q.y * f01.y + q.z * f23.x + q.w * f23.y;
            t += __shfl_xor_sync(0xffffffffu, t, 1);
            t += __shfl_xor_sync(0xffffffffu, t, 2);
            t += __shfl_xor_sync(0xffffffffu, t, 4);
            d = t * scale;
        }
        sc[w] = d;
    }
    float m = -1e30f;
#pragma unroll
    for (int w = 0; w < WMAX; w++) m = fmaxf(m, sc[w]);
    float sum = 0.f;
#pragma unroll
    for (int w = 0; w < WMAX; w++) { sc[w] = expf(sc[w] - m); sum += sc[w]; }
    float inv = 1.f / sum;

    const __half* vb = g_V + ((size_t)b * MM + start) * DATOM;
    float4 acc = make_float4(0.f, 0.f, 0.f, 0.f);
#pragma unroll
    for (int w = 0; w < WMAX; w++) {
        if (w < count) {
            float p = sc[w] * inv;
            uint2 raw = *(const uint2*)(vb + (size_t)w * DATOM + lane * 4);
            float2 f01 = __half22float2(*(__half2*)&raw.x);
            float2 f23 = __half22float2(*(__half2*)&raw.y);
            acc.x = fmaf(p, f01.x, acc.x);
            acc.y = fmaf(p, f01.y, acc.y);
            acc.z = fmaf(p, f23.x, acc.z);
            acc.w = fmaf(p, f23.y, acc.w);
        }
    }
    float msk = tmask[bt];
    float4 g = *(const float4*)(g_G + (size_t)bt * DATOM + lane * 4);
    float ux = acc.x * msk / (1.f + expf(-g.x));
    float uy = acc.y * msk / (1.f + expf(-g.y));
    float uz = acc.z * msk / (1.f + expf(-g.z));
    float uw = acc.w * msk / (1.f + expf(-g.w));
    uint2 hv = make_uint2(pack_h2(ux, uy), pack_h2(uz, uw));
    *(uint2*)(g_U + (size_t)bt * DATOM + lane * 4) = hv;
}

// ==================================================================
// Kernel 6: out = U @ w_o. One 128-col quarter per block (y = 0..3).
// ==================================================================
__global__ void __launch_bounds__(256, 2)
out_mma_kernel(float* __restrict__ out) {
    char* sm = dyn_smem;
    uint32_t sbase = smem_u32(sm);
    int tid = threadIdx.x;
    int warp = tid >> 5, lane = tid & 31;
    size_t rowbase = (size_t)blockIdx.x * 128;
    int colbase = blockIdx.y * 128;

#pragma unroll
    for (int t = 0; t < 8; t++) {
        int j   = tid + t * 256;
        int row = j >> 4;
        int c8  = (j & 15) * 8;
        uint32_t off = (uint32_t)row * KV_STRIDE_B + c8 * 2;
        CP_ASYNC16(sbase + OFF_A + off, g_U + (rowbase + row) * DATOM + c8);
        CP_ASYNC16(sbase + OFF_B + off,
                   g_hwo + (size_t)row * DTOK + colbase + c8);
    }
    CP_COMMIT();
    CP_WAIT0();
    __syncthreads();

    int wm = warp & 3;
    int wn = warp >> 2;
    int lr = lane & 15;
    int lc = lane >> 4;
    uint32_t aAddr = sbase + OFF_A + (uint32_t)(wm * 32 + lr) * KV_STRIDE_B + lc * 16;
    uint32_t bAddr = sbase + OFF_B + (uint32_t)lr * KV_STRIDE_B + (wn * 64 + lc * 8) * 2;

    float c[2][8][4];
#pragma unroll
    for (int mt = 0; mt < 2; mt++)
#pragma unroll
        for (int nt = 0; nt < 8; nt++)
#pragma unroll
            for (int e = 0; e < 4; e++) c[mt][nt][e] = 0.f;

#pragma unroll
    for (int ks = 0; ks < 8; ks++) {
        uint32_t ak = aAddr + ks * 32;
        uint32_t bk = bAddr + ks * 16 * KV_STRIDE_B;
        uint32_t aF[2][4];
        ldm4(aF[0], ak);
        ldm4(aF[1], ak + 16 * KV_STRIDE_B);
        uint32_t b[4][4];
#pragma unroll
        for (int i = 0; i < 4; i++) ldm4t(b[i], bk + i * 32);
#pragma unroll
        for (int mt = 0; mt < 2; mt++)
#pragma unroll
            for (int i = 0; i < 4; i++) {
                mma16816(c[mt][2 * i],     aF[mt], b[i][0], b[i][1]);
                mma16816(c[mt][2 * i + 1], aF[mt], b[i][2], b[i][3]);
            }
    }
    __syncthreads();
    {
        float* stg = (float*)sm;
        int cr = lane >> 2, cc2 = (lane & 3) * 2;
#pragma unroll
        for (int mt = 0; mt < 2; mt++) {
            int r0 = wm * 32 + mt * 16 + cr;
#pragma unroll
            for (int nt = 0; nt < 8; nt++) {
                int cc = wn * 64 + nt * 8 + cc2;
                *(float2*)&stg[r0 * STG_STRIDE + cc] =
                    make_float2(c[mt][nt][0], c[mt][nt][1]);
                *(float2*)&stg[(r0 + 8) * STG_STRIDE + cc] =
                    make_float2(c[mt][nt][2], c[mt][nt][3]);
            }
        }
        __syncthreads();
#pragma unroll
        for (int t = 0; t < 16; t++) {
            int j  = tid + t * 256;
            int r  = j >> 5;
            int c4 = (j & 31) * 4;
            *(float4*)&out[(rowbase + r) * DTOK + colbase + c4] =
                *(float4*)&stg[r * STG_STRIDE + c4];
        }
    }
}

// ==================================================================
// Launch.
// ==================================================================
extern "C" void kernel_launch(void* const* d_in, const int* in_sizes, int n_in,
                              void* d_out, int out_size) {
    const float* s      = (const float*)d_in[0];
    const float* a      = (const float*)d_in[1];
    const int*   starts = (const int*)  d_in[2];
    const int*   counts = (const int*)  d_in[3];
    const float* tmask  = (const float*)d_in[4];
    const float* wq     = (const float*)d_in[5];
    const float* wk     = (const float*)d_in[6];
    const float* wv     = (const float*)d_in[7];
    const float* wg     = (const float*)d_in[8];
    const float* wo     = (const float*)d_in[9];
    const float* lnqg   = (const float*)d_in[10];
    const float* lnqb   = (const float*)d_in[11];
    const float* lnkg   = (const float*)d_in[12];
    const float* lnkb   = (const float*)d_in[13];
    float* out = (float*)d_out;

    cudaFuncSetAttribute(kv_mma_kernel,
                         cudaFuncAttributeMaxDynamicSharedMemorySize, KV_SMEM);
    cudaFuncSetAttribute(qg_mma_kernel,
                         cudaFuncAttributeMaxDynamicSharedMemorySize, GEMM_SMEM);
    cudaFuncSetAttribute(out_mma_kernel,
                         cudaFuncAttributeMaxDynamicSharedMemorySize, GEMM_SMEM);

    wprep_kernel<<<256, 256>>>(wq, wk, wv, wg, wo);
    s_prep_kernel<<<NTOK / 8, 256>>>(s, lnqg, lnqb);
    a_prep_kernel<<<NATOM / 8, 256>>>(a, lnkg, lnkb);
    kv_mma_kernel<<<dim3(NATOM / 128 / KVT, 2), 256, KV_SMEM>>>();
    qg_mma_kernel<<<dim3(NTOK / 128, 2), 256, GEMM_SMEM>>>();
    attn_gate_kernel<<<NTOK / 8, 256>>>(starts, counts, tmask);
    out_mma_kernel<<<dim3(NTOK / 128, 4), 256, GEMM_SMEM>>>(out);
}